// round 10
// baseline (speedup 1.0000x reference)
#include <cuda_runtime.h>
#include <math.h>

#define G   640
#define NXK 320
#define MK  65536
#define NCK 8
#define NTK 8
#define LB  4            // FFT lines per block (one coil-quad)
#define FT  256          // FFT kernel threads
#define SUBP 142         // padded 128-FFT sub-array stride (128 + 8*pad2_per16 - 2)
#define LSB  710         // per-line stride in SB (5 * SUBP)

// ---- scratch (device globals; no runtime allocation) ----
// d_grids: [t][cq][i][j][c4]  (coil quads innermost -> 32B-contiguous scatter targets)
__device__ float2 d_grids[(size_t)NTK * 2 * G * G * 4];        // ~210 MB
// d_buf1:  [t][cq][row][cy][c4]
__device__ float2 d_buf1 [(size_t)NTK * 2 * G * NXK * 4];      // ~105 MB
// d_buf2:  [t][cx][cy][c8]
__device__ float2 d_buf2 [(size_t)NTK * NXK * NXK * NCK];      // ~52 MB
__device__ float2 d_fimg [(size_t)NTK * NXK * NXK];            // ~6.6 MB

__constant__ float2 W5c[5] = {
    { 1.0f,                   0.0f },
    { 0.30901699437494745f,   0.9510565162951535f },
    {-0.8090169943749473f,    0.5877852522924731f },
    {-0.8090169943749475f,   -0.587785252292473f  },
    { 0.30901699437494723f,  -0.9510565162951536f }
};
// w16^j = e^{+2*pi*i*j/16}, j = 0..9
__constant__ float2 W16c[10] = {
    { 1.0f, 0.0f },
    { 0.9238795325112867f,  0.3826834323650898f },
    { 0.7071067811865476f,  0.7071067811865476f },
    { 0.3826834323650898f,  0.9238795325112867f },
    { 0.0f, 1.0f },
    {-0.3826834323650898f,  0.9238795325112867f },
    {-0.7071067811865476f,  0.7071067811865476f },
    {-0.9238795325112867f,  0.3826834323650898f },
    {-1.0f, 0.0f },
    {-0.9238795325112867f, -0.3826834323650898f }
};

__device__ __forceinline__ float2 cadd(float2 a, float2 b) { return make_float2(a.x + b.x, a.y + b.y); }
__device__ __forceinline__ float2 csub(float2 a, float2 b) { return make_float2(a.x - b.x, a.y - b.y); }
__device__ __forceinline__ float2 cmul(float2 a, float2 b) { return make_float2(a.x * b.x - a.y * b.y, a.x * b.y + a.y * b.x); }
__device__ __forceinline__ float2 cmuli(float2 a) { return make_float2(-a.y, a.x); }   // * (+i)

// ---------------- zero grids ----------------
__global__ void zero_kernel() {
    size_t i = (size_t)blockIdx.x * blockDim.x + threadIdx.x;
    float4* p = reinterpret_cast<float4*>(d_grids);
    size_t n4 = (size_t)NTK * 2 * G * G * 4 / 2;
    if (i < n4) p[i] = make_float4(0.f, 0.f, 0.f, 0.f);
}

// ---------------- gridding (scatter, red.add.v4.f32 to contiguous coil quads) ----------------
__device__ __forceinline__ void redv4(float2* p, float2 a, float2 b) {
    asm volatile("red.global.add.v4.f32 [%0], {%1, %2, %3, %4};"
                 :: "l"(p), "f"(a.x), "f"(a.y), "f"(b.x), "f"(b.y) : "memory");
}

__global__ void grid_kernel(const float* __restrict__ kr, const float* __restrict__ ki,
                            const float* __restrict__ traj, const float* __restrict__ dcf) {
    int m = blockIdx.x * blockDim.x + threadIdx.x;
    int t = blockIdx.y;
    if (m >= MK) return;
    float tx = traj[m * 16 + t];
    float ty = traj[m * 16 + 8 + t];
    float w  = dcf[m * 8 + t];

    float u = (tx + 0.5f) * (float)G;
    float v = (ty + 0.5f) * (float)G;
    float u0 = floorf(u), v0 = floorf(v);
    float du = u - u0, dv = v - v0;
    int i0 = ((int)u0) % G; if (i0 < 0) i0 += G;
    int j0 = ((int)v0) % G; if (j0 < 0) j0 += G;
    int i1 = (i0 + 1 == G) ? 0 : i0 + 1;
    int j1 = (j0 + 1 == G) ? 0 : j0 + 1;

    float w00 = (1.f - du) * (1.f - dv) * w;
    float w10 = du * (1.f - dv) * w;
    float w01 = (1.f - du) * dv * w;
    float w11 = du * dv * w;

#pragma unroll
    for (int cq = 0; cq < 2; cq++) {
        float2 d[4];
#pragma unroll
        for (int c4 = 0; c4 < 4; c4++) {
            int c = cq * 4 + c4;
            d[c4] = make_float2(kr[c * MK + m], ki[c * MK + m]);
        }
        float2* base = d_grids + ((size_t)(t * 2 + cq) * G * G) * 4;
        float2* p00 = base + (size_t)(i0 * G + j0) * 4;
        float2* p10 = base + (size_t)(i1 * G + j0) * 4;
        float2* p01 = base + (size_t)(i0 * G + j1) * 4;
        float2* p11 = base + (size_t)(i1 * G + j1) * 4;
#define CORNER(P, W) \
        redv4(P,     make_float2(d[0].x*(W), d[0].y*(W)), make_float2(d[1].x*(W), d[1].y*(W))); \
        redv4(P + 2, make_float2(d[2].x*(W), d[2].y*(W)), make_float2(d[3].x*(W), d[3].y*(W)));
        CORNER(p00, w00)
        CORNER(p10, w10)
        CORNER(p01, w01)
        CORNER(p11, w11)
#undef CORNER
    }
}

// ======== 640-pt FFT (sign = +i, unnormalized): radix-5 -> DIF 8x16 in registers ========
// SA: lines of 640 (stride 640).  SB: padded 128-FFT workspace, addr(pos) = pos + 2*(pos>>4),
// sub-FFT k1 at SUBP*k1, line l at LSB*l.
// Final: 128-FFT result X[k] at padded addr 18*(k&7) + (k>>3).

// Step A: 128 radix-5 DFTs per line + twiddle.  SA -> SB(padded)
__device__ __forceinline__ void step_radix5(const float2* SA, float2* SB, int tid) {
    for (int i = tid; i < LB * 128; i += FT) {
        int l = i >> 7, n2 = i & 127;
        float2 x0 = SA[l * G + n2];
        float2 x1 = SA[l * G + n2 + 128];
        float2 x2 = SA[l * G + n2 + 256];
        float2 x3 = SA[l * G + n2 + 384];
        float2 x4 = SA[l * G + n2 + 512];
        int pa = n2 + 2 * (n2 >> 4);          // padded position of n2
        float2* outb = SB + l * LSB + pa;
#pragma unroll
        for (int k1 = 0; k1 < 5; k1++) {
            float2 acc = x0;
            int r = 0;
            float2 xs[4] = {x1, x2, x3, x4};
#pragma unroll
            for (int n1 = 1; n1 < 5; n1++) {
                r += k1; if (r >= 5) r -= 5;
                float2 wv = W5c[r];
                acc.x += xs[n1 - 1].x * wv.x - xs[n1 - 1].y * wv.y;
                acc.y += xs[n1 - 1].x * wv.y + xs[n1 - 1].y * wv.x;
            }
            float ang = (float)(n2 * k1) * 9.817477042468103e-3f; // 2*pi/640
            float sn, cs; __sincosf(ang, &sn, &cs);
            outb[k1 * SUBP] = make_float2(acc.x * cs - acc.y * sn,
                                          acc.x * sn + acc.y * cs);
        }
    }
}

// Stage 1 (DIF radix-8 over n1, stride 16): in-place in SB
__device__ __forceinline__ void stage_dft8(float2* SB, int tid) {
    const float2 w8_1 = make_float2(0.7071067811865476f,  0.7071067811865476f);
    const float2 w8_3 = make_float2(-0.7071067811865476f, 0.7071067811865476f);
    for (int i = tid; i < LB * 5 * 16; i += FT) {
        int n0 = i & 15, g = i >> 4;
        int f = g % 5, l = g / 5;
        float2* B = SB + l * LSB + f * SUBP + n0;
        float2 a0 = B[0],    a1 = B[18],  a2 = B[36],  a3 = B[54];
        float2 a4 = B[72],   a5 = B[90],  a6 = B[108], a7 = B[126];
        // micro radix-2 stage 1 (n=8,s=1)
        float2 b0 = cadd(a0, a4), b1 = csub(a0, a4);
        float2 b2 = cadd(a1, a5), b3 = cmul(csub(a1, a5), w8_1);
        float2 b4 = cadd(a2, a6), b5 = cmuli(csub(a2, a6));
        float2 b6 = cadd(a3, a7), b7 = cmul(csub(a3, a7), w8_3);
        // micro stage 2 (n=4,s=2)
        float2 c0 = cadd(b0, b4), c2 = csub(b0, b4);
        float2 c1 = cadd(b1, b5), c3 = csub(b1, b5);
        float2 c4 = cadd(b2, b6), c6 = cmuli(csub(b2, b6));
        float2 c5 = cadd(b3, b7), c7 = cmuli(csub(b3, b7));
        // micro stage 3 (n=2,s=4)
        float2 d0 = cadd(c0, c4), d4 = csub(c0, c4);
        float2 d1 = cadd(c1, c5), d5 = csub(c1, c5);
        float2 d2 = cadd(c2, c6), d6 = csub(c2, c6);
        float2 d3 = cadd(c3, c7), d7 = csub(c3, c7);
        // twiddle w128^{n0*r}, r = 1..7, then write back (in place)
        float base = (float)n0 * 4.908738521234052e-2f;  // 2*pi/128
        B[0] = d0;
        float2 dd[7] = {d1, d2, d3, d4, d5, d6, d7};
#pragma unroll
        for (int r = 1; r <= 7; r++) {
            float sn, cs; __sincosf(base * (float)r, &sn, &cs);
            float2 v = dd[r - 1];
            B[18 * r] = make_float2(v.x * cs - v.y * sn, v.x * sn + v.y * cs);
        }
    }
}

// Stage 2 (DFT16 over contiguous 16, no twiddle): in-place in SB via float4
__device__ __forceinline__ void stage_dft16(float2* SB, int tid) {
    for (int i = tid; i < LB * 5 * 8; i += FT) {
        int r = i & 7, g = i >> 3;
        int f = g % 5, l = g / 5;
        float4* B4 = reinterpret_cast<float4*>(SB + l * LSB + f * SUBP + 18 * r);
        float2 a[16];
#pragma unroll
        for (int j = 0; j < 8; j++) {
            float4 v = B4[j];
            a[2 * j]     = make_float2(v.x, v.y);
            a[2 * j + 1] = make_float2(v.z, v.w);
        }
        // micro radix-4 stage A: (n=16,s=1) -> b[4p+k'], twiddle w16^{p k'}
        float2 b[16];
#pragma unroll
        for (int p = 0; p < 4; p++) {
            float2 x0 = a[p], x1 = a[p + 4], x2 = a[p + 8], x3 = a[p + 12];
            float2 t0 = cadd(x0, x2), t1 = csub(x0, x2);
            float2 t2 = cadd(x1, x3), t3 = cmuli(csub(x1, x3));
            float2 y0 = cadd(t0, t2), y1 = cadd(t1, t3);
            float2 y2 = csub(t0, t2), y3 = csub(t1, t3);
            b[4 * p]     = y0;
            b[4 * p + 1] = (p == 0) ? y1 : cmul(y1, W16c[p]);
            b[4 * p + 2] = (p == 0) ? y2 : cmul(y2, W16c[2 * p]);
            b[4 * p + 3] = (p == 0) ? y3 : cmul(y3, W16c[3 * p]);
        }
        // micro radix-4 stage B: (n=4,s=4) -> c[q+4k'], no twiddle
        float2 c[16];
#pragma unroll
        for (int q = 0; q < 4; q++) {
            float2 x0 = b[q], x1 = b[q + 4], x2 = b[q + 8], x3 = b[q + 12];
            float2 t0 = cadd(x0, x2), t1 = csub(x0, x2);
            float2 t2 = cadd(x1, x3), t3 = cmuli(csub(x1, x3));
            c[q]      = cadd(t0, t2);
            c[q + 4]  = cadd(t1, t3);
            c[q + 8]  = csub(t0, t2);
            c[q + 12] = csub(t1, t3);
        }
#pragma unroll
        for (int j = 0; j < 8; j++)
            B4[j] = make_float4(c[2 * j].x, c[2 * j].y, c[2 * j + 1].x, c[2 * j + 1].y);
    }
}

__device__ __forceinline__ void fft640(float2* SA, float2* SB, int tid) {
    step_radix5(SA, SB, tid);  __syncthreads();
    stage_dft8(SB, tid);       __syncthreads();
    stage_dft16(SB, tid);      __syncthreads();
}

// padded address of logical 128-FFT output index k (0..127)
__device__ __forceinline__ int out_addr128(int k) {
    return 18 * (k & 7) + (k >> 3);
}

// ---------------- pass 1: FFT rows, keep cropped 320 columns ----------------
__global__ void fft_rows_kernel() {
    __shared__ __align__(16) float2 SA[LB * G];
    __shared__ __align__(16) float2 SB[LB * LSB];
    int tid = threadIdx.x;
    int tq  = blockIdx.x / G;      // t*2 + cq
    int row = blockIdx.x % G;

    const float2* in = d_grids + ((size_t)tq * G + row) * G * 4;
    for (int v = tid; v < G * 4; v += FT) {
        int c = v & 3, j = v >> 2;
        SA[c * G + j] = in[v];
    }
    __syncthreads();
    fft640(SA, SB, tid);

    float2* out = d_buf1 + ((size_t)tq * G + row) * NXK * 4;
    for (int v = tid; v < NXK * 4; v += FT) {
        int c = v & 3, cy = v >> 2;
        int k = (cy < 160) ? cy + 480 : cy - 160;   // (cy+480) % 640
        out[v] = SB[c * LSB + (k % 5) * SUBP + out_addr128(k / 5)];
    }
}

// ---------------- pass 2: FFT columns, keep cropped 320 rows ----------------
__global__ void fft_cols_kernel() {
    __shared__ __align__(16) float2 SA[LB * G];
    __shared__ __align__(16) float2 SB[LB * LSB];
    int tid = threadIdx.x;
    int tq = blockIdx.x / NXK;
    int cy = blockIdx.x % NXK;

    const float2* in = d_buf1 + (size_t)tq * G * NXK * 4 + (size_t)cy * 4;
    for (int v = tid; v < G * 4; v += FT) {
        int c = v & 3, i = v >> 2;
        SA[c * G + i] = in[(size_t)i * NXK * 4 + c];
    }
    __syncthreads();
    fft640(SA, SB, tid);

    int t = tq >> 1, cq = tq & 1;
    float2* out = d_buf2 + (size_t)t * NXK * NXK * NCK + cq * 4;
    for (int v = tid; v < NXK * 4; v += FT) {
        int c = v & 3, cx = v >> 2;
        int k = (cx < 160) ? cx + 480 : cx - 160;
        out[((size_t)cx * NXK + cy) * NCK + c] = SB[c * LSB + (k % 5) * SUBP + out_addr128(k / 5)];
    }
}

// ---------------- coil combine + sign + deapodization + 1/G^2 ----------------
__global__ void combine_kernel(const float* __restrict__ csr, const float* __restrict__ csi) {
    int pix = blockIdx.x * blockDim.x + threadIdx.x;
    int t = blockIdx.y;
    if (pix >= NXK * NXK) return;
    int cx = pix / NXK, cy = pix % NXK;

    const float4* p = reinterpret_cast<const float4*>(d_buf2 + ((size_t)t * NXK * NXK + pix) * NCK);
    float2 acc = make_float2(0.f, 0.f);
#pragma unroll
    for (int h = 0; h < 4; h++) {            // 2 coils per float4
        float4 vv = p[h];
        int c0 = h * 2, c1 = h * 2 + 1;
        float cr0 = csr[c0 * NXK * NXK + pix], ci0 = csi[c0 * NXK * NXK + pix];
        float cr1 = csr[c1 * NXK * NXK + pix], ci1 = csi[c1 * NXK * NXK + pix];
        acc.x += cr0 * vv.x + ci0 * vv.y + cr1 * vv.z + ci1 * vv.w;
        acc.y += cr0 * vv.y - ci0 * vv.x + cr1 * vv.w - ci1 * vv.z;
    }
    float xv = (float)(cx - 160) * (1.0f / 640.0f);
    float yv = (float)(cy - 160) * (1.0f / 640.0f);
    float sx = (cx == 160) ? 1.0f : sinpif(xv) / (3.14159265358979f * xv);
    float sy = (cy == 160) ? 1.0f : sinpif(yv) / (3.14159265358979f * yv);
    float sgn = ((cx + cy) & 1) ? -1.0f : 1.0f;
    float scale = sgn / (409600.0f * (sx * sx) * (sy * sy));
    d_fimg[(size_t)t * NXK * NXK + pix] = make_float2(acc.x * scale, acc.y * scale);
}

// ---------------- motion warp + frame sum ----------------
__global__ void warp_kernel(const float* __restrict__ motions, float* __restrict__ out) {
    int pix = blockIdx.x * blockDim.x + threadIdx.x;
    if (pix >= NXK * NXK) return;
    int x = pix / NXK, y = pix % NXK;

    float2 acc = make_float2(0.f, 0.f);
#pragma unroll
    for (int t = 0; t < NTK; t++) {
        float f0 = motions[(pix * 2 + 0) * NTK + t];
        float f1 = motions[(pix * 2 + 1) * NTK + t];
        float xs = fminf(fmaxf((float)x + f0, 0.f), 319.f);
        float ys = fminf(fmaxf((float)y + f1, 0.f), 319.f);
        float x0f = floorf(xs), y0f = floorf(ys);
        int x0 = (int)x0f, y0 = (int)y0f;
        int x1 = min(x0 + 1, 319), y1 = min(y0 + 1, 319);
        float dx = xs - x0f, dy = ys - y0f;
        const float2* im = d_fimg + (size_t)t * NXK * NXK;
        float2 v00 = im[x0 * NXK + y0];
        float2 v10 = im[x1 * NXK + y0];
        float2 v01 = im[x0 * NXK + y1];
        float2 v11 = im[x1 * NXK + y1];
        float w00 = (1.f - dx) * (1.f - dy), w10 = dx * (1.f - dy);
        float w01 = (1.f - dx) * dy,         w11 = dx * dy;
        acc.x += w00 * v00.x + w10 * v10.x + w01 * v01.x + w11 * v11.x;
        acc.y += w00 * v00.y + w10 * v10.y + w01 * v01.y + w11 * v11.y;
    }
    out[pix * 2 + 0] = acc.x;
    out[pix * 2 + 1] = acc.y;
}

// ---------------- launch ----------------
extern "C" void kernel_launch(void* const* d_in, const int* in_sizes, int n_in,
                              void* d_out, int out_size) {
    const float* kspace_r = (const float*)d_in[0];
    const float* kspace_i = (const float*)d_in[1];
    const float* traj     = (const float*)d_in[2];
    const float* csm_r    = (const float*)d_in[3];
    const float* csm_i    = (const float*)d_in[4];
    const float* dcf      = (const float*)d_in[5];
    const float* motions  = (const float*)d_in[6];
    float* out = (float*)d_out;

    {
        size_t n4 = (size_t)NTK * 2 * G * G * 4 / 2;
        int thr = 512;
        int blk = (int)((n4 + thr - 1) / thr);
        zero_kernel<<<blk, thr>>>();
    }
    {
        dim3 grid(MK / 256, NTK);
        grid_kernel<<<grid, 256>>>(kspace_r, kspace_i, traj, dcf);
    }
    fft_rows_kernel<<<NTK * 2 * G, FT>>>();
    fft_cols_kernel<<<NTK * 2 * NXK, FT>>>();
    {
        dim3 grid((NXK * NXK + 255) / 256, NTK);
        combine_kernel<<<grid, 256>>>(csm_r, csm_i);
    }
    warp_kernel<<<(NXK * NXK + 255) / 256, 256>>>(motions, out);
}

// round 13
// speedup vs baseline: 1.2380x; 1.2380x over previous
#include <cuda_runtime.h>
#include <math.h>

#define G   640
#define NXK 320
#define MK  65536
#define NCK 8
#define NTK 8
#define LB  4            // FFT lines per block (one coil-quad)
#define FT  256          // FFT kernel threads
#define LS  642          // padded smem line stride (float2) to avoid bank conflicts

// ---- scratch (device globals; no runtime allocation) ----
// d_grids: [t][cq][i][j][c4]  (coil quads innermost -> 32B-contiguous scatter targets)
__device__ float2 d_grids[(size_t)NTK * 2 * G * G * 4];        // ~210 MB
// d_buf1:  [t][cq][row][cy][c4]
__device__ float2 d_buf1 [(size_t)NTK * 2 * G * NXK * 4];      // ~105 MB
// d_buf2:  [t][cx][cy][c8]
__device__ float2 d_buf2 [(size_t)NTK * NXK * NXK * NCK];      // ~52 MB
__device__ float2 d_fimg [(size_t)NTK * NXK * NXK];            // ~6.6 MB

__constant__ float2 W5c[5] = {
    { 1.0f,                   0.0f },
    { 0.30901699437494745f,   0.9510565162951535f },
    {-0.8090169943749473f,    0.5877852522924731f },
    {-0.8090169943749475f,   -0.587785252292473f  },
    { 0.30901699437494723f,  -0.9510565162951536f }
};

__device__ __forceinline__ float2 cadd(float2 a, float2 b) { return make_float2(a.x + b.x, a.y + b.y); }
__device__ __forceinline__ float2 csub(float2 a, float2 b) { return make_float2(a.x - b.x, a.y - b.y); }
__device__ __forceinline__ float2 cmul(float2 a, float2 b) { return make_float2(a.x * b.x - a.y * b.y, a.x * b.y + a.y * b.x); }
__device__ __forceinline__ float2 cmuli(float2 a) { return make_float2(-a.y, a.x); }   // * (+i)

// ---------------- zero grids ----------------
__global__ void zero_kernel() {
    size_t i = (size_t)blockIdx.x * blockDim.x + threadIdx.x;
    float4* p = reinterpret_cast<float4*>(d_grids);
    size_t n4 = (size_t)NTK * 2 * G * G * 4 / 2;
    if (i < n4) p[i] = make_float4(0.f, 0.f, 0.f, 0.f);
}

// ---------------- gridding (scatter, red.add.v4.f32 to contiguous coil quads) ----------------
__device__ __forceinline__ void redv4(float2* p, float2 a, float2 b) {
    asm volatile("red.global.add.v4.f32 [%0], {%1, %2, %3, %4};"
                 :: "l"(p), "f"(a.x), "f"(a.y), "f"(b.x), "f"(b.y) : "memory");
}

__global__ void grid_kernel(const float* __restrict__ kr, const float* __restrict__ ki,
                            const float* __restrict__ traj, const float* __restrict__ dcf) {
    int m = blockIdx.x * blockDim.x + threadIdx.x;
    int t = blockIdx.y;
    if (m >= MK) return;
    float tx = traj[m * 16 + t];
    float ty = traj[m * 16 + 8 + t];
    float w  = dcf[m * 8 + t];

    float u = (tx + 0.5f) * (float)G;
    float v = (ty + 0.5f) * (float)G;
    float u0 = floorf(u), v0 = floorf(v);
    float du = u - u0, dv = v - v0;
    int i0 = ((int)u0) % G; if (i0 < 0) i0 += G;
    int j0 = ((int)v0) % G; if (j0 < 0) j0 += G;
    int i1 = (i0 + 1 == G) ? 0 : i0 + 1;
    int j1 = (j0 + 1 == G) ? 0 : j0 + 1;

    float w00 = (1.f - du) * (1.f - dv) * w;
    float w10 = du * (1.f - dv) * w;
    float w01 = (1.f - du) * dv * w;
    float w11 = du * dv * w;

#pragma unroll
    for (int cq = 0; cq < 2; cq++) {
        float2 d[4];
#pragma unroll
        for (int c4 = 0; c4 < 4; c4++) {
            int c = cq * 4 + c4;
            d[c4] = make_float2(kr[c * MK + m], ki[c * MK + m]);
        }
        float2* base = d_grids + ((size_t)(t * 2 + cq) * G * G) * 4;
        float2* p00 = base + (size_t)(i0 * G + j0) * 4;
        float2* p10 = base + (size_t)(i1 * G + j0) * 4;
        float2* p01 = base + (size_t)(i0 * G + j1) * 4;
        float2* p11 = base + (size_t)(i1 * G + j1) * 4;
#define CORNER(P, W) \
        redv4(P,     make_float2(d[0].x*(W), d[0].y*(W)), make_float2(d[1].x*(W), d[1].y*(W))); \
        redv4(P + 2, make_float2(d[2].x*(W), d[2].y*(W)), make_float2(d[3].x*(W), d[3].y*(W)));
        CORNER(p00, w00)
        CORNER(p10, w10)
        CORNER(p01, w01)
        CORNER(p11, w11)
#undef CORNER
    }
}

// ======== shared FFT building blocks (640 = 5 * 128; sign = +i, unnormalized) =========
// lines live at SA[l*LS + e], e in [0,640)

// Step A: 128 radix-5 DFTs per line + twiddle (one sincos, powers by cmul).
__device__ __forceinline__ void step_radix5(const float2* SA, float2* SB, int tid) {
    for (int i = tid; i < LB * 128; i += FT) {
        int l = i >> 7, n2 = i & 127;
        float2 x0 = SA[l * LS + n2];
        float2 x1 = SA[l * LS + n2 + 128];
        float2 x2 = SA[l * LS + n2 + 256];
        float2 x3 = SA[l * LS + n2 + 384];
        float2 x4 = SA[l * LS + n2 + 512];
        float ang = (float)n2 * 9.817477042468103e-3f;   // 2*pi/640
        float sn, cs; __sincosf(ang, &sn, &cs);
        float2 w1 = make_float2(cs, sn);
        float2 w2 = cmul(w1, w1);
        float2 w3 = cmul(w2, w1);
        float2 w4 = cmul(w2, w2);
        float2 wp[5] = { make_float2(1.f, 0.f), w1, w2, w3, w4 };
#pragma unroll
        for (int k1 = 0; k1 < 5; k1++) {
            float2 acc = x0;
            int r = 0;
            float2 xs[4] = {x1, x2, x3, x4};
#pragma unroll
            for (int n1 = 1; n1 < 5; n1++) {
                r += k1; if (r >= 5) r -= 5;
                float2 wv = W5c[r];
                acc.x += xs[n1 - 1].x * wv.x - xs[n1 - 1].y * wv.y;
                acc.y += xs[n1 - 1].x * wv.y + xs[n1 - 1].y * wv.x;
            }
            SB[l * LS + k1 * 128 + n2] = (k1 == 0) ? acc : cmul(acc, wp[k1]);
        }
    }
}

template<int N_, int S_>
__device__ __forceinline__ void stage_radix4(const float2* src, float2* dst, int tid) {
    const int MH = N_ / 4;
    for (int i = tid; i < LB * 160; i += FT) {
        int l = i / 160, r = i - l * 160;
        int f = r >> 5, b = r & 31;
        int p = b / S_, q = b - p * S_;
        int cb = l * LS + f * 128;
        float2 x0 = src[cb + q + S_ * p];
        float2 x1 = src[cb + q + S_ * (p + MH)];
        float2 x2 = src[cb + q + S_ * (p + 2 * MH)];
        float2 x3 = src[cb + q + S_ * (p + 3 * MH)];
        float2 t0 = cadd(x0, x2);
        float2 t1 = csub(x0, x2);
        float2 t2 = cadd(x1, x3);
        float2 t3 = cmuli(csub(x1, x3)); // +i*(x1-x3)
        float2 y0 = cadd(t0, t2);
        float2 y1 = cadd(t1, t3);
        float2 y2 = csub(t0, t2);
        float2 y3 = csub(t1, t3);
        float ang = 6.283185307179586f / (float)N_ * (float)p;
        float s1, c1; __sincosf(ang, &s1, &c1);
        float c2 = c1 * c1 - s1 * s1, s2 = 2.f * c1 * s1;
        float c3 = c2 * c1 - s2 * s1, s3 = c2 * s1 + s2 * c1;
        int ob = cb + q;
        dst[ob + S_ * (4 * p + 0)] = y0;
        dst[ob + S_ * (4 * p + 1)] = make_float2(y1.x * c1 - y1.y * s1, y1.x * s1 + y1.y * c1);
        dst[ob + S_ * (4 * p + 2)] = make_float2(y2.x * c2 - y2.y * s2, y2.x * s2 + y2.y * c2);
        dst[ob + S_ * (4 * p + 3)] = make_float2(y3.x * c3 - y3.y * s3, y3.x * s3 + y3.y * c3);
    }
}

// Fused final stage: radix4<8,16> + radix2(s=64) == 8-pt DFT on stride-16 chain, in place.
// All twiddles constant (1, w8, i, w8^3). Chains are disjoint per thread -> in-place safe.
__device__ __forceinline__ void stage_fused8(float2* SB, int tid) {
    const float2 w8_1 = make_float2( 0.7071067811865476f, 0.7071067811865476f);
    const float2 w8_3 = make_float2(-0.7071067811865476f, 0.7071067811865476f);
    for (int i = tid; i < LB * 5 * 16; i += FT) {
        int q = i & 15, g = i >> 4;
        int f = g % 5, l = g / 5;
        float2* B = SB + l * LS + f * 128 + q;
        float2 a0 = B[0],   a1 = B[16],  a2 = B[32],  a3 = B[48];
        float2 a4 = B[64],  a5 = B[80],  a6 = B[96],  a7 = B[112];
        // radix4<8,16> p=0 (no twiddle): inputs a0,a2,a4,a6
        float2 t0 = cadd(a0, a4), t1 = csub(a0, a4);
        float2 t2 = cadd(a2, a6), t3 = cmuli(csub(a2, a6));
        float2 b0 = cadd(t0, t2), b1 = cadd(t1, t3);
        float2 b2 = csub(t0, t2), b3 = csub(t1, t3);
        // radix4<8,16> p=1 (twiddles w8^k): inputs a1,a3,a5,a7
        float2 u0 = cadd(a1, a5), u1 = csub(a1, a5);
        float2 u2 = cadd(a3, a7), u3 = cmuli(csub(a3, a7));
        float2 b4 = cadd(u0, u2);
        float2 b5 = cmul(cadd(u1, u3), w8_1);
        float2 b6 = cmuli(csub(u0, u2));
        float2 b7 = cmul(csub(u1, u3), w8_3);
        // radix2 final (no twiddle): out[r] = b_r + b_{r+4}; out[r+4] = b_r - b_{r+4}
        B[0]   = cadd(b0, b4);  B[64]  = csub(b0, b4);
        B[16]  = cadd(b1, b5);  B[80]  = csub(b1, b5);
        B[32]  = cadd(b2, b6);  B[96]  = csub(b2, b6);
        B[48]  = cadd(b3, b7);  B[112] = csub(b3, b7);
    }
}

__device__ __forceinline__ void fft640(float2* SA, float2* SB, int tid) {
    step_radix5(SA, SB, tid);          __syncthreads();
    stage_radix4<128, 1>(SB, SA, tid); __syncthreads();
    stage_radix4<32, 4>(SA, SB, tid);  __syncthreads();
    stage_fused8(SB, tid);             __syncthreads();
    // X[5*k2+k1] = SB[l*LS + k1*128 + k2]
}

// ---------------- pass 1: FFT rows, keep cropped 320 columns ----------------
__global__ void fft_rows_kernel() {
    __shared__ float2 SA[LB * LS];
    __shared__ float2 SB[LB * LS];
    int tid = threadIdx.x;
    int tq  = blockIdx.x / G;      // t*2 + cq
    int row = blockIdx.x % G;

    const float2* in = d_grids + ((size_t)tq * G + row) * G * 4;
    for (int v = tid; v < G * 4; v += FT) {
        int c = v & 3, j = v >> 2;
        SA[c * LS + j] = in[v];
    }
    __syncthreads();
    fft640(SA, SB, tid);

    float2* out = d_buf1 + ((size_t)tq * G + row) * NXK * 4;
    for (int v = tid; v < NXK * 4; v += FT) {
        int c = v & 3, cy = v >> 2;
        int k = (cy < 160) ? cy + 480 : cy - 160;   // (cy+480) % 640
        out[v] = SB[c * LS + (k % 5) * 128 + k / 5];
    }
}

// ---------------- pass 2: FFT columns, keep cropped 320 rows ----------------
__global__ void fft_cols_kernel() {
    __shared__ float2 SA[LB * LS];
    __shared__ float2 SB[LB * LS];
    int tid = threadIdx.x;
    int tq = blockIdx.x / NXK;
    int cy = blockIdx.x % NXK;

    const float2* in = d_buf1 + (size_t)tq * G * NXK * 4 + (size_t)cy * 4;
    for (int v = tid; v < G * 4; v += FT) {
        int c = v & 3, i = v >> 2;
        SA[c * LS + i] = in[(size_t)i * NXK * 4 + c];
    }
    __syncthreads();
    fft640(SA, SB, tid);

    int t = tq >> 1, cq = tq & 1;
    float2* out = d_buf2 + (size_t)t * NXK * NXK * NCK + cq * 4;
    for (int v = tid; v < NXK * 4; v += FT) {
        int c = v & 3, cx = v >> 2;
        int k = (cx < 160) ? cx + 480 : cx - 160;
        out[((size_t)cx * NXK + cy) * NCK + c] = SB[c * LS + (k % 5) * 128 + k / 5];
    }
}

// ---------------- coil combine + sign + deapodization + 1/G^2 ----------------
__global__ void combine_kernel(const float* __restrict__ csr, const float* __restrict__ csi) {
    int pix = blockIdx.x * blockDim.x + threadIdx.x;
    int t = blockIdx.y;
    if (pix >= NXK * NXK) return;
    int cx = pix / NXK, cy = pix % NXK;

    const float4* p = reinterpret_cast<const float4*>(d_buf2 + ((size_t)t * NXK * NXK + pix) * NCK);
    float2 acc = make_float2(0.f, 0.f);
#pragma unroll
    for (int h = 0; h < 4; h++) {            // 2 coils per float4
        float4 vv = p[h];
        int c0 = h * 2, c1 = h * 2 + 1;
        float cr0 = csr[c0 * NXK * NXK + pix], ci0 = csi[c0 * NXK * NXK + pix];
        float cr1 = csr[c1 * NXK * NXK + pix], ci1 = csi[c1 * NXK * NXK + pix];
        acc.x += cr0 * vv.x + ci0 * vv.y + cr1 * vv.z + ci1 * vv.w;
        acc.y += cr0 * vv.y - ci0 * vv.x + cr1 * vv.w - ci1 * vv.z;
    }
    float xv = (float)(cx - 160) * (1.0f / 640.0f);
    float yv = (float)(cy - 160) * (1.0f / 640.0f);
    float sx = (cx == 160) ? 1.0f : sinpif(xv) / (3.14159265358979f * xv);
    float sy = (cy == 160) ? 1.0f : sinpif(yv) / (3.14159265358979f * yv);
    float sgn = ((cx + cy) & 1) ? -1.0f : 1.0f;
    float scale = sgn / (409600.0f * (sx * sx) * (sy * sy));
    d_fimg[(size_t)t * NXK * NXK + pix] = make_float2(acc.x * scale, acc.y * scale);
}

// ---------------- motion warp + frame sum ----------------
__global__ void warp_kernel(const float* __restrict__ motions, float* __restrict__ out) {
    int pix = blockIdx.x * blockDim.x + threadIdx.x;
    if (pix >= NXK * NXK) return;
    int x = pix / NXK, y = pix % NXK;

    float2 acc = make_float2(0.f, 0.f);
#pragma unroll
    for (int t = 0; t < NTK; t++) {
        float f0 = motions[(pix * 2 + 0) * NTK + t];
        float f1 = motions[(pix * 2 + 1) * NTK + t];
        float xs = fminf(fmaxf((float)x + f0, 0.f), 319.f);
        float ys = fminf(fmaxf((float)y + f1, 0.f), 319.f);
        float x0f = floorf(xs), y0f = floorf(ys);
        int x0 = (int)x0f, y0 = (int)y0f;
        int x1 = min(x0 + 1, 319), y1 = min(y0 + 1, 319);
        float dx = xs - x0f, dy = ys - y0f;
        const float2* im = d_fimg + (size_t)t * NXK * NXK;
        float2 v00 = im[x0 * NXK + y0];
        float2 v10 = im[x1 * NXK + y0];
        float2 v01 = im[x0 * NXK + y1];
        float2 v11 = im[x1 * NXK + y1];
        float w00 = (1.f - dx) * (1.f - dy), w10 = dx * (1.f - dy);
        float w01 = (1.f - dx) * dy,         w11 = dx * dy;
        acc.x += w00 * v00.x + w10 * v10.x + w01 * v01.x + w11 * v11.x;
        acc.y += w00 * v00.y + w10 * v10.y + w01 * v01.y + w11 * v11.y;
    }
    out[pix * 2 + 0] = acc.x;
    out[pix * 2 + 1] = acc.y;
}

// ---------------- launch ----------------
extern "C" void kernel_launch(void* const* d_in, const int* in_sizes, int n_in,
                              void* d_out, int out_size) {
    const float* kspace_r = (const float*)d_in[0];
    const float* kspace_i = (const float*)d_in[1];
    const float* traj     = (const float*)d_in[2];
    const float* csm_r    = (const float*)d_in[3];
    const float* csm_i    = (const float*)d_in[4];
    const float* dcf      = (const float*)d_in[5];
    const float* motions  = (const float*)d_in[6];
    float* out = (float*)d_out;

    {
        size_t n4 = (size_t)NTK * 2 * G * G * 4 / 2;
        int thr = 512;
        int blk = (int)((n4 + thr - 1) / thr);
        zero_kernel<<<blk, thr>>>();
    }
    {
        dim3 grid(MK / 256, NTK);
        grid_kernel<<<grid, 256>>>(kspace_r, kspace_i, traj, dcf);
    }
    fft_rows_kernel<<<NTK * 2 * G, FT>>>();
    fft_cols_kernel<<<NTK * 2 * NXK, FT>>>();
    {
        dim3 grid((NXK * NXK + 255) / 256, NTK);
        combine_kernel<<<grid, 256>>>(csm_r, csm_i);
    }
    warp_kernel<<<(NXK * NXK + 255) / 256, 256>>>(motions, out);
}